// round 2
// baseline (speedup 1.0000x reference)
#include <cuda_runtime.h>

typedef unsigned long long ull;

#define IH 400
#define IW 400
#define KS 11
#define PAD 5
#define CIN 3
#define F1 128
#define F2 64
#define F3 8
#define TILE 16
#define TW (TILE + KS - 1)   // 26

// ---- smem layout (floats) ----
// sx  : [0,     2048)   x halo tile, 3*26*26 = 2028
// sw  : [2048,  13664)  W1 group slice, 363*32
// sW2 : [13664, 21856)  128*64
// sW3 : [21856, 22368)  64*8
// sb1 : [22368, 22496)
// sb2 : [22496, 22560)
// sb3 : [22560, 22568)
#define OFF_SW  2048
#define OFF_W2  13664
#define OFF_W3  21856
#define OFF_B1  22368
#define OFF_B2  22496
#define OFF_B3  22560
#define SMEM_FLOATS 22576
#define SMEM_BYTES (SMEM_FLOATS * 4)

// packed fp32x2 FMA: acc += a * b  (two IEEE fp32 FMAs per issue)
#define FMA2(acc, a, b) \
    asm("fma.rn.f32x2 %0, %1, %2, %0;" : "+l"(acc) : "l"(a), "l"(b))

__device__ __forceinline__ ull packdup(float v) {
    ull r;
    asm("mov.b64 %0, {%1, %1};" : "=l"(r) : "f"(v));
    return r;
}
__device__ __forceinline__ ull packf(float lo, float hi) {
    ull r;
    asm("mov.b64 %0, {%1, %2};" : "=l"(r) : "f"(lo), "f"(hi));
    return r;
}
__device__ __forceinline__ float2 unpk(ull v) {
    float2 r;
    asm("mov.b64 {%0, %1}, %2;" : "=f"(r.x), "=f"(r.y) : "l"(v));
    return r;
}

// ---------------------------------------------------------------------------
// Fully fused: 11x11 conv(3->128)+leaky -> 128->64 +leaky -> 64->8 -> L2 norm.
// Block = 256 threads = 16x16 pixel tile, 1 pixel/thread.
// h2 (64 accumulators) lives in registers as 32 f32x2; each 32-channel h1
// group is folded into h2 immediately, so h1 never touches global memory.
// ---------------------------------------------------------------------------
__global__ void __launch_bounds__(256) fused_k(const float* __restrict__ x,
                                               const float* __restrict__ W1,
                                               const float* __restrict__ b1,
                                               const float* __restrict__ W2,
                                               const float* __restrict__ b2,
                                               const float* __restrict__ W3,
                                               const float* __restrict__ b3,
                                               float* __restrict__ out)
{
    extern __shared__ float smem[];
    float* sx  = smem;
    float* sw  = smem + OFF_SW;
    float* sW2 = smem + OFF_W2;
    float* sW3 = smem + OFF_W3;
    float* sb1 = smem + OFF_B1;
    float* sb2 = smem + OFF_B2;
    float* sb3 = smem + OFF_B3;

    const int tid = threadIdx.x;
    const int x0 = blockIdx.x * TILE - PAD;
    const int y0 = blockIdx.y * TILE - PAD;

    // ---- stage x halo tile (zero-padded) ----
    for (int i = tid; i < CIN * TW * TW; i += 256) {
        int c = i / (TW * TW);
        int rem = i - c * (TW * TW);
        int r = rem / TW, col = rem - r * TW;
        int gy = y0 + r, gx = x0 + col;
        float v = 0.f;
        if ((unsigned)gy < (unsigned)IH && (unsigned)gx < (unsigned)IW)
            v = x[(c * IH + gy) * IW + gx];
        sx[i] = v;
    }
    // ---- stage W2 / W3 / biases ----
    for (int i = tid; i < F1 * F2; i += 256) sW2[i] = W2[i];
    for (int i = tid; i < F2 * F3; i += 256) sW3[i] = W3[i];
    if (tid < F1) sb1[tid] = b1[tid];
    if (tid < F2) sb2[tid] = b2[tid];
    if (tid < F3) sb3[tid] = b3[tid];

    const int tx = tid & 15, ty = tid >> 4;

    // h2 accumulators: 64 channels as 32 packed pairs, init with b2
    ull h2[32];
    __syncthreads();
#pragma unroll
    for (int q = 0; q < 32; q++) h2[q] = packf(sb2[2 * q], sb2[2 * q + 1]);

    // ---- loop over 4 groups of 32 output channels of layer 1 ----
    for (int g = 0; g < 4; g++) {
        const int base = g * 32;

        __syncthreads();   // everyone done with previous sw contents
        for (int i = tid; i < 363 * 32; i += 256) {
            int f = i >> 5, ch = i & 31;
            sw[i] = W1[f * F1 + base + ch];
        }
        __syncthreads();

        // conv partial: 32 channels as 16 packed pairs
        ull acc[16];
#pragma unroll
        for (int q = 0; q < 16; q++) acc[q] = 0ULL;  // (+0.f, +0.f)

#pragma unroll 1
        for (int c = 0; c < CIN; c++) {
#pragma unroll 1
            for (int ki = 0; ki < KS; ki++) {
                const float* xrow = &sx[c * (TW * TW) + (ty + ki) * TW + tx];
                const ulonglong2* wrow =
                    (const ulonglong2*)&sw[(c * (KS * KS) + ki * KS) << 5];
#pragma unroll
                for (int kj = 0; kj < KS; kj++) {
                    ull xv = packdup(xrow[kj]);
                    const ulonglong2* wv = wrow + kj * 8;
#pragma unroll
                    for (int q = 0; q < 8; q++) {
                        ulonglong2 w = wv[q];   // LDS.128 broadcast: 4 channels
                        FMA2(acc[2 * q],     xv, w.x);
                        FMA2(acc[2 * q + 1], xv, w.y);
                    }
                }
            }
        }

        // bias + leaky, then fold this h1 group into the h2 accumulators
#pragma unroll
        for (int q = 0; q < 16; q++) {
            float2 h = unpk(acc[q]);
            int k0 = base + 2 * q;
            float t0 = h.x + sb1[k0];
            float t1 = h.y + sb1[k0 + 1];
            t0 = t0 > 0.f ? t0 : 0.01f * t0;
            t1 = t1 > 0.f ? t1 : 0.01f * t1;
            ull a0 = packdup(t0);
            ull a1 = packdup(t1);
            const ulonglong2* w2r0 = (const ulonglong2*)&sW2[k0 * F2];
            const ulonglong2* w2r1 = (const ulonglong2*)&sW2[(k0 + 1) * F2];
#pragma unroll
            for (int cc = 0; cc < 16; cc++) {
                ulonglong2 wa = w2r0[cc];
                FMA2(h2[2 * cc],     a0, wa.x);
                FMA2(h2[2 * cc + 1], a0, wa.y);
                ulonglong2 wb = w2r1[cc];
                FMA2(h2[2 * cc],     a1, wb.x);
                FMA2(h2[2 * cc + 1], a1, wb.y);
            }
        }
    }

    // ---- leaky on h2, layer 3, L2 normalize ----
    float h2f[F2];
#pragma unroll
    for (int q = 0; q < 32; q++) {
        float2 h = unpk(h2[q]);
        h2f[2 * q]     = h.x > 0.f ? h.x : 0.01f * h.x;
        h2f[2 * q + 1] = h.y > 0.f ? h.y : 0.01f * h.y;
    }

    float v[F3];
#pragma unroll
    for (int e = 0; e < F3; e++) v[e] = sb3[e];
#pragma unroll 8
    for (int k = 0; k < F2; k++) {
        float hk = h2f[k];
        const float4* wr = (const float4*)&sW3[k * F3];
        float4 w0 = wr[0], w1 = wr[1];
        v[0] += hk * w0.x; v[1] += hk * w0.y; v[2] += hk * w0.z; v[3] += hk * w0.w;
        v[4] += hk * w1.x; v[5] += hk * w1.y; v[6] += hk * w1.z; v[7] += hk * w1.w;
    }

    float ss = 0.f;
#pragma unroll
    for (int e = 0; e < F3; e++) ss += v[e] * v[e];
    float n = fmaxf(sqrtf(ss), 1e-12f);
    float inv = 1.0f / n;

    const int px = blockIdx.x * TILE + tx;
    const int py = blockIdx.y * TILE + ty;
    float4* o = (float4*)(out + (size_t)(py * IW + px) * F3);
    float4 o0, o1;
    o0.x = v[0] * inv; o0.y = v[1] * inv; o0.z = v[2] * inv; o0.w = v[3] * inv;
    o1.x = v[4] * inv; o1.y = v[5] * inv; o1.z = v[6] * inv; o1.w = v[7] * inv;
    o[0] = o0;
    o[1] = o1;
}

// ---------------------------------------------------------------------------
extern "C" void kernel_launch(void* const* d_in, const int* in_sizes, int n_in,
                              void* d_out, int out_size)
{
    const float* x  = (const float*)d_in[0];   // [1,3,400,400]
    const float* W1 = (const float*)d_in[1];   // [363,128]
    const float* b1 = (const float*)d_in[2];   // [128]
    const float* W2 = (const float*)d_in[3];   // [128,64]
    const float* b2 = (const float*)d_in[4];   // [64]
    const float* W3 = (const float*)d_in[5];   // [64,8]
    const float* b3 = (const float*)d_in[6];   // [8]
    float* out = (float*)d_out;                // [400,400,8]

    cudaFuncSetAttribute(fused_k, cudaFuncAttributeMaxDynamicSharedMemorySize,
                         SMEM_BYTES);

    dim3 grid(IW / TILE, IH / TILE);   // 25 x 25
    fused_k<<<grid, 256, SMEM_BYTES>>>(x, W1, b1, W2, b2, W3, b3, out);
}

// round 3
// speedup vs baseline: 1.6271x; 1.6271x over previous
#include <cuda_runtime.h>

typedef unsigned long long ull;

#define IH 400
#define IW 400
#define KS 11
#define PAD 5
#define CIN 3
#define F1 128
#define F2 64
#define F3 8
#define TILE 16
#define TW (TILE + KS - 1)   // 26

// ---- smem layout (floats) ----
#define OFF_SW  2048            // W1 group slice 363*32
#define OFF_W2  13664           // 128*64
#define OFF_W3  21856           // 64*8
#define OFF_B1  22368
#define OFF_B2  22496
#define OFF_B3  22560
#define SMEM_FLOATS 22576
#define SMEM_BYTES (SMEM_FLOATS * 4)

#define FMA2(acc, a, b) \
    asm("fma.rn.f32x2 %0, %1, %2, %0;" : "+l"(acc) : "l"(a), "l"(b))

__device__ __forceinline__ ull packdup(float v) {
    ull r; asm("mov.b64 %0, {%1, %1};" : "=l"(r) : "f"(v)); return r;
}
__device__ __forceinline__ ull packf(float lo, float hi) {
    ull r; asm("mov.b64 %0, {%1, %2};" : "=l"(r) : "f"(lo), "f"(hi)); return r;
}
__device__ __forceinline__ float2 unpk(ull v) {
    float2 r; asm("mov.b64 {%0, %1}, %2;" : "=f"(r.x), "=f"(r.y) : "l"(v)); return r;
}
__device__ __forceinline__ float lrelu(float t) { return t > 0.f ? t : 0.01f * t; }

// final 64->8 + L2 normalize for one pixel
__device__ __forceinline__ void tail_px(const ull* h2, const float* sW3,
                                        const float* sb3, float* optr)
{
    float h2f[F2];
#pragma unroll
    for (int q = 0; q < 32; q++) {
        float2 h = unpk(h2[q]);
        h2f[2 * q]     = lrelu(h.x);
        h2f[2 * q + 1] = lrelu(h.y);
    }
    float v[F3];
#pragma unroll
    for (int e = 0; e < F3; e++) v[e] = sb3[e];
#pragma unroll 8
    for (int k = 0; k < F2; k++) {
        float hk = h2f[k];
        const float4* wr = (const float4*)&sW3[k * F3];
        float4 w0 = wr[0], w1 = wr[1];
        v[0] += hk * w0.x; v[1] += hk * w0.y; v[2] += hk * w0.z; v[3] += hk * w0.w;
        v[4] += hk * w1.x; v[5] += hk * w1.y; v[6] += hk * w1.z; v[7] += hk * w1.w;
    }
    float ss = 0.f;
#pragma unroll
    for (int e = 0; e < F3; e++) ss += v[e] * v[e];
    float inv = 1.0f / fmaxf(sqrtf(ss), 1e-12f);
    float4* o = (float4*)optr;
    float4 o0, o1;
    o0.x = v[0] * inv; o0.y = v[1] * inv; o0.z = v[2] * inv; o0.w = v[3] * inv;
    o1.x = v[4] * inv; o1.y = v[5] * inv; o1.z = v[6] * inv; o1.w = v[7] * inv;
    o[0] = o0; o[1] = o1;
}

// ---------------------------------------------------------------------------
// Fully fused, 2 pixels per thread (rows ty and ty+8 of a 16x16 tile).
// Every weight LDS.128 feeds FMAs for BOTH pixels -> LDS:FMA ratio halved.
// 128-thread blocks: 2 blocks/SM resident even at 255 regs.
// ---------------------------------------------------------------------------
__global__ void __launch_bounds__(128, 2) fused_k(const float* __restrict__ x,
                                                  const float* __restrict__ W1,
                                                  const float* __restrict__ b1,
                                                  const float* __restrict__ W2,
                                                  const float* __restrict__ b2,
                                                  const float* __restrict__ W3,
                                                  const float* __restrict__ b3,
                                                  float* __restrict__ out)
{
    extern __shared__ float smem[];
    float* sx  = smem;
    float* sw  = smem + OFF_SW;
    float* sW2 = smem + OFF_W2;
    float* sW3 = smem + OFF_W3;
    float* sb1 = smem + OFF_B1;
    float* sb2 = smem + OFF_B2;
    float* sb3 = smem + OFF_B3;

    const int tid = threadIdx.x;
    const int x0 = blockIdx.x * TILE - PAD;
    const int y0 = blockIdx.y * TILE - PAD;

    // stage x halo tile (zero-padded), 3*26*26 = 2028
    for (int i = tid; i < CIN * TW * TW; i += 128) {
        int c = i / (TW * TW);
        int rem = i - c * (TW * TW);
        int r = rem / TW, col = rem - r * TW;
        int gy = y0 + r, gx = x0 + col;
        float v = 0.f;
        if ((unsigned)gy < (unsigned)IH && (unsigned)gx < (unsigned)IW)
            v = x[(c * IH + gy) * IW + gx];
        sx[i] = v;
    }
    for (int i = tid; i < F1 * F2; i += 128) sW2[i] = W2[i];
    for (int i = tid; i < F2 * F3; i += 128) sW3[i] = W3[i];
    if (tid < F1) sb1[tid] = b1[tid];
    if (tid < F2) sb2[tid] = b2[tid];
    if (tid < F3) sb3[tid] = b3[tid];

    const int tx = tid & 15, ty = tid >> 4;   // ty in 0..7

    ull h2a[32], h2b[32];
    __syncthreads();
#pragma unroll
    for (int q = 0; q < 32; q++) {
        ull bv = packf(sb2[2 * q], sb2[2 * q + 1]);
        h2a[q] = bv; h2b[q] = bv;
    }

    for (int g = 0; g < 4; g++) {
        const int base = g * 32;

        __syncthreads();
        for (int i = tid; i < 363 * 32; i += 128) {
            int f = i >> 5, ch = i & 31;
            sw[i] = W1[f * F1 + base + ch];
        }
        __syncthreads();

        ull aa[16], ab[16];
#pragma unroll
        for (int q = 0; q < 16; q++) { aa[q] = 0ULL; ab[q] = 0ULL; }

#pragma unroll 1
        for (int c = 0; c < CIN; c++) {
#pragma unroll 1
            for (int ki = 0; ki < KS; ki++) {
                const float* xra = &sx[c * (TW * TW) + (ty + ki) * TW + tx];
                const float* xrb = xra + 8 * TW;
                const ulonglong2* wrow =
                    (const ulonglong2*)&sw[(c * (KS * KS) + ki * KS) << 5];
#pragma unroll
                for (int kj = 0; kj < KS; kj++) {
                    ull xva = packdup(xra[kj]);
                    ull xvb = packdup(xrb[kj]);
                    const ulonglong2* wv = wrow + kj * 8;
#pragma unroll
                    for (int q = 0; q < 8; q++) {
                        ulonglong2 w = wv[q];   // LDS.128 broadcast, 4 channels
                        FMA2(aa[2 * q],     xva, w.x);
                        FMA2(aa[2 * q + 1], xva, w.y);
                        FMA2(ab[2 * q],     xvb, w.x);
                        FMA2(ab[2 * q + 1], xvb, w.y);
                    }
                }
            }
        }

        // bias + leaky + fold into h2 for both pixels
#pragma unroll
        for (int q = 0; q < 16; q++) {
            int k0 = base + 2 * q;
            float2 ha = unpk(aa[q]);
            float2 hb = unpk(ab[q]);
            float b0 = sb1[k0], b1v = sb1[k0 + 1];
            ull ta0 = packdup(lrelu(ha.x + b0));
            ull ta1 = packdup(lrelu(ha.y + b1v));
            ull tb0 = packdup(lrelu(hb.x + b0));
            ull tb1 = packdup(lrelu(hb.y + b1v));
            const ulonglong2* w2r0 = (const ulonglong2*)&sW2[k0 * F2];
            const ulonglong2* w2r1 = (const ulonglong2*)&sW2[(k0 + 1) * F2];
#pragma unroll
            for (int cc = 0; cc < 16; cc++) {
                ulonglong2 wa = w2r0[cc];
                FMA2(h2a[2 * cc],     ta0, wa.x);
                FMA2(h2a[2 * cc + 1], ta0, wa.y);
                FMA2(h2b[2 * cc],     tb0, wa.x);
                FMA2(h2b[2 * cc + 1], tb0, wa.y);
                ulonglong2 wb = w2r1[cc];
                FMA2(h2a[2 * cc],     ta1, wb.x);
                FMA2(h2a[2 * cc + 1], ta1, wb.y);
                FMA2(h2b[2 * cc],     tb1, wb.x);
                FMA2(h2b[2 * cc + 1], tb1, wb.y);
            }
        }
    }

    const int px = blockIdx.x * TILE + tx;
    const int pya = blockIdx.y * TILE + ty;
    const int pyb = pya + 8;
    tail_px(h2a, sW3, sb3, out + (size_t)(pya * IW + px) * F3);
    tail_px(h2b, sW3, sb3, out + (size_t)(pyb * IW + px) * F3);
}

// ---------------------------------------------------------------------------
extern "C" void kernel_launch(void* const* d_in, const int* in_sizes, int n_in,
                              void* d_out, int out_size)
{
    const float* x  = (const float*)d_in[0];
    const float* W1 = (const float*)d_in[1];
    const float* b1 = (const float*)d_in[2];
    const float* W2 = (const float*)d_in[3];
    const float* b2 = (const float*)d_in[4];
    const float* W3 = (const float*)d_in[5];
    const float* b3 = (const float*)d_in[6];
    float* out = (float*)d_out;

    cudaFuncSetAttribute(fused_k, cudaFuncAttributeMaxDynamicSharedMemorySize,
                         SMEM_BYTES);
    dim3 grid(IW / TILE, IH / TILE);   // 25 x 25
    fused_k<<<grid, 128, SMEM_BYTES>>>(x, W1, b1, W2, b2, W3, b3, out);
}

// round 5
// speedup vs baseline: 3.5207x; 2.1638x over previous
#include <cuda_runtime.h>
#include <cuda_bf16.h>
#include <cstdint>

#define IH 400
#define IW 400
#define NPIX 160000
#define F1 128
#define F2 64
#define F3 8

// A tile: 128 rows (pixels) x 128 k (bf16), row padded to 272B for conflict-free ldmatrix
#define AROW 272
#define OFF_AH 0
#define OFF_AL 34816
#define OFF_H2S 69632            // 4 warps x 32px x 65 f32
#define OFF_B1S 102912
#define OFF_B2S 103424
#define OFF_B3S 103680
#define OFF_W3S 103712
#define SMEM_BYTES 105760

// Pre-packed weight fragments (uint4 = {bh0,bh1,bl0,bl1} per lane)
__device__ uint4 g_B1f[3 * 8 * 16 * 32];   // [chunk][kt][ni][lane]
__device__ uint4 g_W2f[8 * 8 * 32];        // [kt][ni2][lane]

// ---------------- helpers ----------------
__device__ __forceinline__ uint32_t smem_u32(const void* p) {
    uint32_t a;
    asm("{ .reg .u64 t; cvta.to.shared.u64 t, %1; cvt.u32.u64 %0, t; }"
        : "=r"(a) : "l"(p));
    return a;
}
// pack two f32 -> bf16x2 (upper = hi_val, lower = lo_val)
__device__ __forceinline__ uint32_t cvt2(float hi_val, float lo_val) {
    uint32_t r;
    asm("cvt.rn.bf16x2.f32 %0, %1, %2;" : "=r"(r) : "f"(hi_val), "f"(lo_val));
    return r;
}
// split (v0,v1) into hi bf16x2 + residual-lo bf16x2 (lower lane = v0)
__device__ __forceinline__ void split2(float v0, float v1, uint32_t& h, uint32_t& l) {
    h = cvt2(v1, v0);
    float f0 = __uint_as_float(h << 16);
    float f1 = __uint_as_float(h & 0xFFFF0000u);
    l = cvt2(v1 - f1, v0 - f0);
}
__device__ __forceinline__ float lrelu(float t) { return t > 0.f ? t : 0.01f * t; }

#define LDM4(r, addr) \
    asm("ldmatrix.sync.aligned.m8n8.x4.shared.b16 {%0,%1,%2,%3}, [%4];" \
        : "=r"((r)[0]), "=r"((r)[1]), "=r"((r)[2]), "=r"((r)[3]) : "r"(addr))

#define MMA(d, a, b0_, b1_) \
    asm("mma.sync.aligned.m16n8k16.row.col.f32.bf16.bf16.f32 " \
        "{%0,%1,%2,%3},{%4,%5,%6,%7},{%8,%9},{%0,%1,%2,%3};" \
        : "+f"((d).x), "+f"((d).y), "+f"((d).z), "+f"((d).w) \
        : "r"((a)[0]), "r"((a)[1]), "r"((a)[2]), "r"((a)[3]), "r"(b0_), "r"(b1_))

// ---------------------------------------------------------------------------
// Prep: pack W1 (363x128) and W2 (128x64) into mma.sync b-fragment layout,
// bf16 hi + residual lo, zero-padded K. One uint4 slot per (tile, lane).
// ---------------------------------------------------------------------------
__global__ void prep_k(const float* __restrict__ W1, const float* __restrict__ W2) {
    int t = blockIdx.x * 256 + threadIdx.x;
    if (t >= 12288 + 2048) return;
    if (t < 12288) {
        int lane = t & 31, ni = (t >> 5) & 15, kt = (t >> 9) & 7, chunk = t >> 12;
        int c = lane & 3, g = lane >> 2;
        int n = ni * 8 + g;
        int k0 = kt * 16 + 2 * c;
        float v00 = 0.f, v01 = 0.f, v10 = 0.f, v11 = 0.f;
        if (k0 + 1 < 121) {
            v00 = W1[(chunk * 121 + k0) * F1 + n];
            v01 = W1[(chunk * 121 + k0 + 1) * F1 + n];
        } else if (k0 < 121) {
            v00 = W1[(chunk * 121 + k0) * F1 + n];
        }
        if (k0 + 9 < 121) {
            v10 = W1[(chunk * 121 + k0 + 8) * F1 + n];
            v11 = W1[(chunk * 121 + k0 + 9) * F1 + n];
        } else if (k0 + 8 < 121) {
            v10 = W1[(chunk * 121 + k0 + 8) * F1 + n];
        }
        uint4 o;
        split2(v00, v01, o.x, o.z);
        split2(v10, v11, o.y, o.w);
        g_B1f[t] = o;
    } else {
        int t2 = t - 12288;
        int lane = t2 & 31, ni2 = (t2 >> 5) & 7, kt = t2 >> 8;
        int c = lane & 3, g = lane >> 2;
        int n = ni2 * 8 + g;
        int k0 = kt * 16 + 2 * c;
        float v00 = W2[k0 * F2 + n];
        float v01 = W2[(k0 + 1) * F2 + n];
        float v10 = W2[(k0 + 8) * F2 + n];
        float v11 = W2[(k0 + 9) * F2 + n];
        uint4 o;
        split2(v00, v01, o.x, o.z);
        split2(v10, v11, o.y, o.w);
        g_W2f[t2] = o;
    }
}

// ---------------------------------------------------------------------------
// Main: CTA = 128 px (4 warps, 32 px each, fully warp-independent after the
// initial staging sync). Layer1+2 via mma.sync bf16 split-3; tail via FFMA.
// ---------------------------------------------------------------------------
__global__ void __launch_bounds__(128) main_k(const float* __restrict__ x,
                                              const float* __restrict__ b1,
                                              const float* __restrict__ b2,
                                              const float* __restrict__ b3,
                                              const float* __restrict__ W3,
                                              float* __restrict__ out)
{
    extern __shared__ char smem[];
    float* sb1 = (float*)(smem + OFF_B1S);
    float* sb2 = (float*)(smem + OFF_B2S);
    float* sb3 = (float*)(smem + OFF_B3S);
    float* sW3 = (float*)(smem + OFF_W3S);

    const int tid = threadIdx.x;
    const int w = tid >> 5;
    const int lane = tid & 31;
    const int c4 = lane & 3, g = lane >> 2;
    const uint32_t sbase = smem_u32(smem);

    if (tid < F1) sb1[tid] = b1[tid];
    if (tid < F2) sb2[tid] = b2[tid];
    if (tid < F3) sb3[tid] = b3[tid];
    for (int i = tid; i < F2 * F3; i += 128) sW3[i] = W3[i];
    __syncthreads();   // only block-wide sync in the kernel

    const int p = blockIdx.x * 128 + tid;
    const int py = p / IW;
    const int px = p - py * IW;
    const int px5 = px - 5;

    // per-thread A row pointers (thread builds row tid)
    __nv_bfloat16* rowAh = (__nv_bfloat16*)(smem + OFF_AH + tid * AROW);
    __nv_bfloat16* rowAl = (__nv_bfloat16*)(smem + OFF_AL + tid * AROW);

    // ldmatrix base addresses for this lane (mi=0); +16*AROW for mi=1
    const uint32_t lm_base = sbase + OFF_AH +
        (32 * w + (lane & 15)) * AROW + (lane >> 4) * 16;

    float4 d1[2][16];
#pragma unroll
    for (int mi = 0; mi < 2; mi++)
#pragma unroll
        for (int ni = 0; ni < 16; ni++) d1[mi][ni] = make_float4(0.f, 0.f, 0.f, 0.f);

    // ================= layer 1: K = 3 chunks x 128 (121 valid) =============
#pragma unroll 1
    for (int chunk = 0; chunk < 3; chunk++) {
        const float* xc = x + chunk * (IH * IW);

        // build A rows (own pixel), bf16 hi + residual lo
#pragma unroll 1
        for (int ki = 0; ki < 11; ki++) {
            int gy = py + ki - 5;
            bool rowok = (unsigned)gy < (unsigned)IH;
            const float* xr = xc + gy * IW + px5;
            int kb = ki * 11;
#pragma unroll
            for (int kj = 0; kj < 11; kj++) {
                float v = 0.f;
                if (rowok && (unsigned)(px5 + kj) < (unsigned)IW) v = __ldg(xr + kj);
                __nv_bfloat16 h = __float2bfloat16(v);
                __nv_bfloat16 l = __float2bfloat16(v - __bfloat162float(h));
                rowAh[kb + kj] = h;
                rowAl[kb + kj] = l;
            }
        }
#pragma unroll
        for (int k = 121; k < 128; k++) {
            rowAh[k] = __float2bfloat16(0.f);
            rowAl[k] = __float2bfloat16(0.f);
        }
        __syncwarp();

#pragma unroll 1
        for (int kt = 0; kt < 8; kt++) {
            uint32_t ah0[4], ah1[4], al0[4], al1[4];
            uint32_t a0 = lm_base + kt * 32;
            LDM4(ah0, a0);
            LDM4(ah1, a0 + 16 * AROW);
            LDM4(al0, a0 + (OFF_AL - OFF_AH));
            LDM4(al1, a0 + (OFF_AL - OFF_AH) + 16 * AROW);
            const uint4* bp = g_B1f + ((chunk * 8 + kt) * 16) * 32 + lane;
#pragma unroll
            for (int ni = 0; ni < 16; ni++) {
                uint4 bb = __ldg(bp + ni * 32);
                MMA(d1[0][ni], ah0, bb.x, bb.y);
                MMA(d1[1][ni], ah1, bb.x, bb.y);
                MMA(d1[0][ni], ah0, bb.z, bb.w);
                MMA(d1[1][ni], ah1, bb.z, bb.w);
                MMA(d1[0][ni], al0, bb.x, bb.y);
                MMA(d1[1][ni], al1, bb.x, bb.y);
            }
        }
        __syncwarp();
    }

    // ============ layer 2: bias+leaky+split in regs, mma 128->64 ===========
    float4 d2[2][8];
#pragma unroll
    for (int mi = 0; mi < 2; mi++)
#pragma unroll
        for (int ni = 0; ni < 8; ni++) d2[mi][ni] = make_float4(0.f, 0.f, 0.f, 0.f);

#pragma unroll
    for (int kt = 0; kt < 8; kt++) {
        uint32_t ah[2][4], al[2][4];
#pragma unroll
        for (int half = 0; half < 2; half++) {
            int ni = 2 * kt + half;
            float2 bb = *(const float2*)&sb1[8 * ni + 2 * c4];
#pragma unroll
            for (int mi = 0; mi < 2; mi++) {
                float4 D = d1[mi][ni];
                float v0 = lrelu(D.x + bb.x);
                float v1 = lrelu(D.y + bb.y);
                float v2 = lrelu(D.z + bb.x);
                float v3 = lrelu(D.w + bb.y);
                split2(v0, v1, ah[mi][half * 2], al[mi][half * 2]);
                split2(v2, v3, ah[mi][half * 2 + 1], al[mi][half * 2 + 1]);
            }
        }
        const uint4* wp = g_W2f + (kt * 8) * 32 + lane;
#pragma unroll
        for (int ni = 0; ni < 8; ni++) {
            uint4 ww = __ldg(wp + ni * 32);
            MMA(d2[0][ni], ah[0], ww.x, ww.y);
            MMA(d2[1][ni], ah[1], ww.x, ww.y);
            MMA(d2[0][ni], ah[0], ww.z, ww.w);
            MMA(d2[1][ni], ah[1], ww.z, ww.w);
            MMA(d2[0][ni], al[0], ww.x, ww.y);
            MMA(d2[1][ni], al[1], ww.x, ww.y);
        }
    }

    // ============ h2 -> padded smem, per-pixel 64->8 + normalize ===========
    float* h2s = (float*)(smem + OFF_H2S) + w * (32 * 65);
#pragma unroll
    for (int ni = 0; ni < 8; ni++) {
        float2 bb = *(const float2*)&sb2[8 * ni + 2 * c4];
        int ch = 8 * ni + 2 * c4;
#pragma unroll
        for (int mi = 0; mi < 2; mi++) {
            float4 D = d2[mi][ni];
            int r0 = 16 * mi + g;
            h2s[r0 * 65 + ch]       = lrelu(D.x + bb.x);
            h2s[r0 * 65 + ch + 1]   = lrelu(D.y + bb.y);
            h2s[(r0 + 8) * 65 + ch]     = lrelu(D.z + bb.x);
            h2s[(r0 + 8) * 65 + ch + 1] = lrelu(D.w + bb.y);
        }
    }
    __syncwarp();

    const float* myrow = h2s + lane * 65;
    float v[F3];
#pragma unroll
    for (int e = 0; e < F3; e++) v[e] = sb3[e];
#pragma unroll 8
    for (int k = 0; k < F2; k++) {
        float hk = myrow[k];
        const float4* wr = (const float4*)&sW3[k * F3];
        float4 w0 = wr[0], w1 = wr[1];
        v[0] += hk * w0.x; v[1] += hk * w0.y; v[2] += hk * w0.z; v[3] += hk * w0.w;
        v[4] += hk * w1.x; v[5] += hk * w1.y; v[6] += hk * w1.z; v[7] += hk * w1.w;
    }
    float ss = 0.f;
#pragma unroll
    for (int e = 0; e < F3; e++) ss += v[e] * v[e];
    float inv = 1.0f / fmaxf(sqrtf(ss), 1e-12f);

    float4* o = (float4*)(out + (size_t)p * F3);
    float4 o0, o1;
    o0.x = v[0] * inv; o0.y = v[1] * inv; o0.z = v[2] * inv; o0.w = v[3] * inv;
    o1.x = v[4] * inv; o1.y = v[5] * inv; o1.z = v[6] * inv; o1.w = v[7] * inv;
    o[0] = o0; o[1] = o1;
}

// ---------------------------------------------------------------------------
extern "C" void kernel_launch(void* const* d_in, const int* in_sizes, int n_in,
                              void* d_out, int out_size)
{
    const float* x  = (const float*)d_in[0];
    const float* W1 = (const float*)d_in[1];
    const float* b1 = (const float*)d_in[2];
    const float* W2 = (const float*)d_in[3];
    const float* b2 = (const float*)d_in[4];
    const float* W3 = (const float*)d_in[5];
    const float* b3 = (const float*)d_in[6];
    float* out = (float*)d_out;

    prep_k<<<(12288 + 2048 + 255) / 256, 256>>>(W1, W2);

    cudaFuncSetAttribute(main_k, cudaFuncAttributeMaxDynamicSharedMemorySize,
                         SMEM_BYTES);
    main_k<<<NPIX / 128, 128, SMEM_BYTES>>>(x, b1, b2, b3, W3, out);
}